// round 1
// baseline (speedup 1.0000x reference)
#include <cuda_runtime.h>
#include <math.h>
#include <stdint.h>

#define Bsz 64
#define CHN 512
#define TDm 256
#define NH 4
#define DHd 64
#define TLAT 1000
#define TTXT 512
#define SCALE_ATT 0.0625f

// ---------------- scratch (device globals; allocation-free) ----------------
__device__ float g_Q[(size_t)Bsz * NH * TLAT * DHd];   // (B,H,Tq,DH) rope'd
__device__ float g_K[(size_t)Bsz * NH * TTXT * DHd];   // (B,H,Tk,DH) rope'd
__device__ float g_V[(size_t)Bsz * NH * TTXT * DHd];   // (B,H,Tk,DH)
__device__ float g_O[(size_t)Bsz * TLAT * TDm];        // (B,Tq,TD) attn out

// ---------------------------------------------------------------------------
// QKV projection: C[t,d] = sum_c A[b,c,t] * W[d,c] + bias[d], optional RoPE,
// write to (B,H,M,DH).  Tile 64(t) x 64(d=one head), Ktile=32, 256 thr, 4x4.
// which: 0 -> g_Q, 1 -> g_K, 2 -> g_V
// ---------------------------------------------------------------------------
__global__ void __launch_bounds__(256) proj_kernel(
    const float* __restrict__ A,      // (B, Kdim, M)
    const float* __restrict__ W,      // (TD, Kdim)
    const float* __restrict__ bias,   // (TD)
    const float* __restrict__ theta,  // (32)
    const float* __restrict__ inc,    // (1000)
    int M, int Kdim, float inv_len, int doRope, int which)
{
    __shared__ float As[32][64];
    __shared__ float Bs[32][64];
    __shared__ float Cs[64][65];

    const int b  = blockIdx.z;
    const int h  = blockIdx.y;
    const int t0 = blockIdx.x * 64;
    const int d0 = h * 64;
    const int tid = threadIdx.x;
    const int tx = tid & 15, ty = tid >> 4;

    const float* Ab = A + (size_t)b * Kdim * M;
    float* outp = (which == 0) ? g_Q : (which == 1) ? g_K : g_V;

    float acc[4][4];
#pragma unroll
    for (int i = 0; i < 4; i++)
#pragma unroll
        for (int j = 0; j < 4; j++) acc[i][j] = 0.f;

    for (int k0 = 0; k0 < Kdim; k0 += 32) {
        // As[kk][tt] = A[b, k0+kk, t0+tt]  (coalesced along t)
#pragma unroll
        for (int p = 0; p < 8; p++) {
            int kk = (tid >> 6) + p * 4;
            int tt = tid & 63;
            int t  = t0 + tt;
            As[kk][tt] = (t < M) ? Ab[(size_t)(k0 + kk) * M + t] : 0.f;
        }
        // Bs[kk][dd] = W[d0+dd, k0+kk]    (coalesced along c)
#pragma unroll
        for (int p = 0; p < 8; p++) {
            int kk = tid & 31;
            int dd = (tid >> 5) + p * 8;
            Bs[kk][dd] = W[(size_t)(d0 + dd) * Kdim + k0 + kk];
        }
        __syncthreads();
#pragma unroll
        for (int kk = 0; kk < 32; kk++) {
            float4 a4 = *(const float4*)&As[kk][ty * 4];
            float4 b4 = *(const float4*)&Bs[kk][tx * 4];
            float av[4] = {a4.x, a4.y, a4.z, a4.w};
            float bv[4] = {b4.x, b4.y, b4.z, b4.w};
#pragma unroll
            for (int i = 0; i < 4; i++)
#pragma unroll
                for (int j = 0; j < 4; j++) acc[i][j] += av[i] * bv[j];
        }
        __syncthreads();
    }

    // stage (bias added pre-RoPE, matching reference)
#pragma unroll
    for (int i = 0; i < 4; i++)
#pragma unroll
        for (int j = 0; j < 4; j++)
            Cs[ty * 4 + i][tx * 4 + j] = acc[i][j] + bias[d0 + tx * 4 + j];
    __syncthreads();

    const size_t base = ((size_t)(b * NH + h)) * (size_t)M * DHd;
#pragma unroll
    for (int i = 0; i < 4; i++) {
        int r = ty * 4 + i;
        int t = t0 + r;
        if (t >= M) continue;
        float pos = inc[t] * inv_len;
#pragma unroll
        for (int j = 0; j < 4; j++) {
            int c = tx * 4 + j;
            float v;
            if (doRope) {
                int jj = c & 31;
                float ang = pos * theta[jj];
                float sv, cv;
                sincosf(ang, &sv, &cv);
                float x1 = Cs[r][jj];
                float x2 = Cs[r][jj + 32];
                v = (c < 32) ? (x1 * cv - x2 * sv) : (x1 * sv + x2 * cv);
            } else {
                v = Cs[r][c];
            }
            outp[base + (size_t)t * DHd + c] = v;
        }
    }
}

// ---------------------------------------------------------------------------
// Flash-style attention: block = (b, h, 64 q rows); loop 8 k-tiles of 64.
// 256 threads, thread = 4 rows x 4 cols. Online softmax with explicit mask
// (p forced to 0 for masked keys: avoids exp(-big - (-big)) = 1 trap).
// Dynamic smem: Qs/Ks/Vs/Ps each [64][65] + mask[64] = 66816 B.
// ---------------------------------------------------------------------------
__global__ void __launch_bounds__(256) attn_kernel(const int* __restrict__ tmask)
{
    extern __shared__ float sm[];
    float (*Qs)[65] = (float(*)[65])(sm);
    float (*Ks)[65] = (float(*)[65])(sm + 64 * 65);
    float (*Vs)[65] = (float(*)[65])(sm + 2 * 64 * 65);
    float (*Ps)[65] = (float(*)[65])(sm + 3 * 64 * 65);
    float* Ms       = sm + 4 * 64 * 65;

    const int qt = blockIdx.x, h = blockIdx.y, b = blockIdx.z;
    const int tid = threadIdx.x;
    const int tx = tid & 15, ty = tid >> 4;

    const float* Qb = g_Q + ((size_t)(b * NH + h)) * TLAT * DHd;
    const float* Kb = g_K + ((size_t)(b * NH + h)) * TTXT * DHd;
    const float* Vb = g_V + ((size_t)(b * NH + h)) * TTXT * DHd;

    // load Q tile (zero-fill OOB rows)
#pragma unroll
    for (int p = 0; p < 16; p++) {
        int r = (tid >> 6) + p * 4;
        int c = tid & 63;
        int t = qt * 64 + r;
        Qs[r][c] = (t < TLAT) ? Qb[(size_t)t * DHd + c] : 0.f;
    }

    float m[4], l[4], acc[4][4];
#pragma unroll
    for (int i = 0; i < 4; i++) {
        m[i] = -1e30f; l[i] = 0.f;
#pragma unroll
        for (int j = 0; j < 4; j++) acc[i][j] = 0.f;
    }

    for (int kt = 0; kt < TTXT / 64; kt++) {
#pragma unroll
        for (int p = 0; p < 16; p++) {
            int r = (tid >> 6) + p * 4;
            int c = tid & 63;
            size_t gi = (size_t)(kt * 64 + r) * DHd + c;
            Ks[r][c] = Kb[gi];
            Vs[r][c] = Vb[gi];
        }
        if (tid < 64) Ms[tid] = (float)tmask[b * TTXT + kt * 64 + tid];
        __syncthreads();

        // S = Q K^T
        float s[4][4];
#pragma unroll
        for (int i = 0; i < 4; i++)
#pragma unroll
            for (int j = 0; j < 4; j++) s[i][j] = 0.f;
#pragma unroll 8
        for (int d = 0; d < 64; d++) {
            float qv[4], kv[4];
#pragma unroll
            for (int i = 0; i < 4; i++) qv[i] = Qs[ty * 4 + i][d];
#pragma unroll
            for (int j = 0; j < 4; j++) kv[j] = Ks[tx * 4 + j][d];
#pragma unroll
            for (int i = 0; i < 4; i++)
#pragma unroll
                for (int j = 0; j < 4; j++) s[i][j] += qv[i] * kv[j];
        }

        float vmask[4];
#pragma unroll
        for (int j = 0; j < 4; j++) vmask[j] = Ms[tx * 4 + j];

#pragma unroll
        for (int i = 0; i < 4; i++) {
            float rm = -1e30f;
#pragma unroll
            for (int j = 0; j < 4; j++) {
                s[i][j] = (vmask[j] != 0.f) ? s[i][j] * SCALE_ATT : -1e30f;
                rm = fmaxf(rm, s[i][j]);
            }
            // max over the 16 threads sharing this row (lanes form 16-groups)
#pragma unroll
            for (int off = 8; off > 0; off >>= 1)
                rm = fmaxf(rm, __shfl_xor_sync(0xffffffffu, rm, off));
            float mnew = fmaxf(m[i], rm);
            float corr = __expf(m[i] - mnew);
            float rs = 0.f;
            float p[4];
#pragma unroll
            for (int j = 0; j < 4; j++) {
                p[j] = (vmask[j] != 0.f) ? __expf(s[i][j] - mnew) : 0.f;
                rs += p[j];
            }
#pragma unroll
            for (int off = 8; off > 0; off >>= 1)
                rs += __shfl_xor_sync(0xffffffffu, rs, off);
            l[i] = l[i] * corr + rs;
            m[i] = mnew;
#pragma unroll
            for (int j = 0; j < 4; j++) {
                acc[i][j] *= corr;
                Ps[ty * 4 + i][tx * 4 + j] = p[j];
            }
        }
        __syncthreads();

        // O += P V
#pragma unroll 8
        for (int kk = 0; kk < 64; kk++) {
            float pv[4], vv[4];
#pragma unroll
            for (int i = 0; i < 4; i++) pv[i] = Ps[ty * 4 + i][kk];
#pragma unroll
            for (int j = 0; j < 4; j++) vv[j] = Vs[kk][tx * 4 + j];
#pragma unroll
            for (int i = 0; i < 4; i++)
#pragma unroll
                for (int j = 0; j < 4; j++) acc[i][j] += pv[i] * vv[j];
        }
        __syncthreads();
    }

#pragma unroll
    for (int i = 0; i < 4; i++) {
        int t = qt * 64 + ty * 4 + i;
        if (t >= TLAT) continue;
        float invl = 1.f / l[i];
#pragma unroll
        for (int j = 0; j < 4; j++)
            g_O[((size_t)b * TLAT + t) * TDm + h * DHd + tx * 4 + j] = acc[i][j] * invl;
    }
}

// ---------------------------------------------------------------------------
// Output projection + residual + mask:
// out[b,c,t] = (x[b,c,t] + bo[c] + sum_d O[b,t,d]*Wo[c,d]) * lmask[b,t]
// Tile 64(t) x 64(c), Ktile=32, 256 thr, 4x4; smem-staged transpose on write.
// ---------------------------------------------------------------------------
__global__ void __launch_bounds__(256) oproj_kernel(
    const float* __restrict__ Wo,     // (CH, TD)
    const float* __restrict__ bo,     // (CH)
    const float* __restrict__ x,      // (B, CH, TLAT)
    const float* __restrict__ lmask,  // (B, 1, TLAT)
    float* __restrict__ out)          // (B, CH, TLAT)
{
    __shared__ float As[32][65];
    __shared__ float Bs[32][65];
    __shared__ float Cs[64][65];

    const int b  = blockIdx.z;
    const int t0 = blockIdx.x * 64;
    const int c0 = blockIdx.y * 64;
    const int tid = threadIdx.x;
    const int tx = tid & 15, ty = tid >> 4;

    const float* Oa = g_O + (size_t)b * TLAT * TDm;

    float acc[4][4];
#pragma unroll
    for (int i = 0; i < 4; i++)
#pragma unroll
        for (int j = 0; j < 4; j++) acc[i][j] = 0.f;

    for (int k0 = 0; k0 < TDm; k0 += 32) {
#pragma unroll
        for (int p = 0; p < 8; p++) {
            int kk = tid & 31;
            int rr = (tid >> 5) + p * 8;
            int t  = t0 + rr;
            As[kk][rr] = (t < TLAT) ? Oa[(size_t)t * TDm + k0 + kk] : 0.f;
            Bs[kk][rr] = Wo[(size_t)(c0 + rr) * TDm + k0 + kk];
        }
        __syncthreads();
#pragma unroll
        for (int kk = 0; kk < 32; kk++) {
            float av[4], bv[4];
#pragma unroll
            for (int i = 0; i < 4; i++) av[i] = As[kk][ty * 4 + i];
#pragma unroll
            for (int j = 0; j < 4; j++) bv[j] = Bs[kk][tx * 4 + j];
#pragma unroll
            for (int i = 0; i < 4; i++)
#pragma unroll
                for (int j = 0; j < 4; j++) acc[i][j] += av[i] * bv[j];
        }
        __syncthreads();
    }

#pragma unroll
    for (int i = 0; i < 4; i++)
#pragma unroll
        for (int j = 0; j < 4; j++)
            Cs[ty * 4 + i][tx * 4 + j] = acc[i][j];
    __syncthreads();

    int tt = tid & 63;
    int t  = t0 + tt;
    if (t < TLAT) {
        float lm = lmask[(size_t)b * TLAT + t];
#pragma unroll
        for (int q = 0; q < 16; q++) {
            int cc = (tid >> 6) + q * 4;
            int c  = c0 + cc;
            size_t idx = ((size_t)b * CHN + c) * TLAT + t;
            out[idx] = (x[idx] + bo[c] + Cs[tt][cc]) * lm;
        }
    }
}

// ---------------------------------------------------------------------------
extern "C" void kernel_launch(void* const* d_in, const int* in_sizes, int n_in,
                              void* d_out, int out_size)
{
    const float* x     = (const float*)d_in[0];
    const float* temb  = (const float*)d_in[1];
    const float* lmask = (const float*)d_in[2];
    const int*   tmask = (const int*)d_in[3];
    const float* Wq    = (const float*)d_in[4];
    const float* bq    = (const float*)d_in[5];
    const float* Wk    = (const float*)d_in[6];
    const float* bk    = (const float*)d_in[7];
    const float* Wv    = (const float*)d_in[8];
    const float* bv    = (const float*)d_in[9];
    const float* Wo    = (const float*)d_in[10];
    const float* bo    = (const float*)d_in[11];
    const float* theta = (const float*)d_in[12];
    const float* inc   = (const float*)d_in[13];
    float* out = (float*)d_out;

    // Q projection + RoPE: M=1000, K=512
    proj_kernel<<<dim3(16, NH, Bsz), 256>>>(x, Wq, bq, theta, inc,
                                            TLAT, CHN, 1.f / (float)TLAT, 1, 0);
    // K projection + RoPE: M=512, K=256
    proj_kernel<<<dim3(8, NH, Bsz), 256>>>(temb, Wk, bk, theta, inc,
                                           TTXT, TDm, 1.f / (float)TTXT, 1, 1);
    // V projection: M=512, K=256
    proj_kernel<<<dim3(8, NH, Bsz), 256>>>(temb, Wv, bv, theta, inc,
                                           TTXT, TDm, 1.f / (float)TTXT, 0, 2);

    // attention
    const int smem_attn = (4 * 64 * 65 + 64) * (int)sizeof(float);  // 66816 B
    cudaFuncSetAttribute(attn_kernel, cudaFuncAttributeMaxDynamicSharedMemorySize,
                         smem_attn);
    attn_kernel<<<dim3(16, NH, Bsz), 256, smem_attn>>>(tmask);

    // output projection + residual + mask
    oproj_kernel<<<dim3(16, 8, Bsz), 256>>>(Wo, bo, x, lmask, out);
}

// round 2
// speedup vs baseline: 5.9358x; 5.9358x over previous
#include <cuda_runtime.h>
#include <cuda_bf16.h>
#include <math.h>
#include <stdint.h>

typedef __nv_bfloat16 bf16;

#define Bsz 64
#define CHN 512
#define TDm 256
#define NH 4
#define DHd 64
#define TLAT 1000
#define TQPAD 1024
#define TTXT 512
#define SCALE_ATT 0.0625f

// ---------------- scratch (device globals; allocation-free) ----------------
__device__ bf16 g_xT[(size_t)Bsz * TQPAD * CHN];      // (B,1024,512) x transposed
__device__ bf16 g_tT[(size_t)Bsz * TTXT * TDm];       // (B,512,256)  temb transposed
__device__ bf16 g_Qb[(size_t)Bsz * NH * TQPAD * DHd]; // (B,H,1024,64) rope'd
__device__ bf16 g_Kb[(size_t)Bsz * NH * TTXT * DHd];  // (B,H,512,64) rope'd
__device__ bf16 g_Vb[(size_t)Bsz * NH * DHd * TTXT];  // (B,H,64,512) transposed
__device__ bf16 g_Ob[(size_t)Bsz * TQPAD * TDm];      // (B,1024,256) attn out
__device__ bf16 g_Wqb[TDm * CHN];
__device__ bf16 g_Wkb[TDm * TDm];
__device__ bf16 g_Wvb[TDm * TDm];
__device__ bf16 g_Wob[CHN * TDm];

// ---------------------------------------------------------------------------
__device__ __forceinline__ void mma_bf16(float c[4], const uint32_t a[4],
                                         const uint32_t b[2]) {
    asm volatile(
        "mma.sync.aligned.m16n8k16.row.col.f32.bf16.bf16.f32 "
        "{%0,%1,%2,%3}, {%4,%5,%6,%7}, {%8,%9}, {%0,%1,%2,%3};\n"
        : "+f"(c[0]), "+f"(c[1]), "+f"(c[2]), "+f"(c[3])
        : "r"(a[0]), "r"(a[1]), "r"(a[2]), "r"(a[3]), "r"(b[0]), "r"(b[1]));
}

__device__ __forceinline__ uint32_t packbf2(float lo, float hi) {
    uint32_t r;
    asm("cvt.rn.bf16x2.f32 %0, %1, %2;" : "=r"(r) : "f"(hi), "f"(lo));
    return r;
}

// ---------------------------------------------------------------------------
// transpose+convert: in (B,D1,D2) f32 -> out (B,D2pad,D1) bf16; dst 0=g_xT 1=g_tT
// ---------------------------------------------------------------------------
__global__ void __launch_bounds__(256) transpose_bf(
    const float* __restrict__ in, int D1, int D2, int D2pad, int dst)
{
    __shared__ float tile[32][33];
    const int b = blockIdx.z;
    const int j0 = blockIdx.x * 32;   // D2
    const int i0 = blockIdx.y * 32;   // D1
    const int tx = threadIdx.x, ty = threadIdx.y;  // (32, 8)
    const float* inb = in + (size_t)b * D1 * D2;
#pragma unroll
    for (int p = 0; p < 4; p++) {
        int r = i0 + ty + p * 8;
        int j = j0 + tx;
        tile[ty + p * 8][tx] = (j < D2) ? inb[(size_t)r * D2 + j] : 0.f;
    }
    __syncthreads();
    bf16* out = (dst == 0) ? g_xT : g_tT;
    bf16* outb = out + (size_t)b * D2pad * D1;
#pragma unroll
    for (int p = 0; p < 4; p++) {
        int j = j0 + ty + p * 8;
        outb[(size_t)j * D1 + i0 + tx] = __float2bfloat16(tile[tx][ty + p * 8]);
    }
}

// ---------------------------------------------------------------------------
__global__ void __launch_bounds__(256) conv_weights(
    const float* __restrict__ Wq, const float* __restrict__ Wk,
    const float* __restrict__ Wv, const float* __restrict__ Wo)
{
    int i = blockIdx.x * 256 + threadIdx.x;
    if (i < TDm * CHN) g_Wqb[i] = __float2bfloat16(Wq[i]);
    if (i < TDm * TDm) {
        g_Wkb[i] = __float2bfloat16(Wk[i]);
        g_Wvb[i] = __float2bfloat16(Wv[i]);
    }
    if (i < CHN * TDm) g_Wob[i] = __float2bfloat16(Wo[i]);
}

// ---------------------------------------------------------------------------
// Projection GEMM (bf16 HMMA): C[t,d] = A[t,:] . W[d,:] + bias, RoPE epilogue.
// CTA tile 128(M=t) x 64(N=d, one head). 8 warps: warp tile 32x32.
// mode: 0=Q(rope, g_Qb) 1=K(rope, g_Kb) 2=V(no rope, g_Vb transposed)
// ---------------------------------------------------------------------------
__global__ void __launch_bounds__(256) proj_mma(
    const float* __restrict__ bias, const float* __restrict__ theta,
    const float* __restrict__ inc, int Mpad, int M, int Kdim,
    float inv_len, int mode)
{
    __shared__ __align__(16) char smraw[33280];
    bf16 (*As)[72] = (bf16(*)[72])smraw;                   // 128x72 = 18432 B
    bf16 (*Bs)[72] = (bf16(*)[72])(smraw + 128 * 72 * 2);  //  64x72 =  9216 B
    float (*Cs)[65] = (float(*)[65])smraw;                 // 128x65 = 33280 B

    const int b = blockIdx.z, h = blockIdx.y;
    const int t0 = blockIdx.x * 128;
    const int tid = threadIdx.x;
    const int wid = tid >> 5, lane = tid & 31;
    const int g = lane >> 2, tig = lane & 3;
    const int m0 = (wid >> 1) * 32, n0 = (wid & 1) * 32;

    const bf16* A = (mode == 0) ? g_xT : g_tT;
    const bf16* W = (mode == 0) ? g_Wqb : (mode == 1) ? g_Wkb : g_Wvb;
    const bf16* Ab = A + ((size_t)b * Mpad + t0) * Kdim;
    const bf16* Wb = W + (size_t)(h * 64) * Kdim;

    float acc[2][4][4] = {};

    for (int k0 = 0; k0 < Kdim; k0 += 64) {
#pragma unroll
        for (int p = 0; p < 4; p++) {
            int idx = tid + p * 256;
            int r = idx >> 3, c8 = (idx & 7) * 8;
            *(uint4*)&As[r][c8] = *(const uint4*)&Ab[(size_t)r * Kdim + k0 + c8];
        }
#pragma unroll
        for (int p = 0; p < 2; p++) {
            int idx = tid + p * 256;
            int r = idx >> 3, c8 = (idx & 7) * 8;
            *(uint4*)&Bs[r][c8] = *(const uint4*)&Wb[(size_t)r * Kdim + k0 + c8];
        }
        __syncthreads();
#pragma unroll
        for (int kc = 0; kc < 4; kc++) {
            uint32_t am[2][4];
#pragma unroll
            for (int ms = 0; ms < 2; ms++) {
                int r = m0 + ms * 16 + g;
                am[ms][0] = *(const uint32_t*)&As[r][kc * 16 + 2 * tig];
                am[ms][1] = *(const uint32_t*)&As[r + 8][kc * 16 + 2 * tig];
                am[ms][2] = *(const uint32_t*)&As[r][kc * 16 + 8 + 2 * tig];
                am[ms][3] = *(const uint32_t*)&As[r + 8][kc * 16 + 8 + 2 * tig];
            }
#pragma unroll
            for (int ns = 0; ns < 4; ns++) {
                uint32_t bb[2];
                int nr = n0 + ns * 8 + g;
                bb[0] = *(const uint32_t*)&Bs[nr][kc * 16 + 2 * tig];
                bb[1] = *(const uint32_t*)&Bs[nr][kc * 16 + 8 + 2 * tig];
                mma_bf16(acc[0][ns], am[0], bb);
                mma_bf16(acc[1][ns], am[1], bb);
            }
        }
        __syncthreads();
    }

    // stage to smem with bias (pre-RoPE, matching reference)
#pragma unroll
    for (int ms = 0; ms < 2; ms++)
#pragma unroll
        for (int ns = 0; ns < 4; ns++) {
            int r = m0 + ms * 16 + g;
            int c = n0 + ns * 8 + 2 * tig;
            float bv0 = bias[h * 64 + c], bv1 = bias[h * 64 + c + 1];
            Cs[r][c]         = acc[ms][ns][0] + bv0;
            Cs[r][c + 1]     = acc[ms][ns][1] + bv1;
            Cs[r + 8][c]     = acc[ms][ns][2] + bv0;
            Cs[r + 8][c + 1] = acc[ms][ns][3] + bv1;
        }
    __syncthreads();

    if (mode < 2) {
        bf16* outp = ((mode == 0) ? g_Qb : g_Kb) +
                     ((size_t)(b * NH + h) * Mpad + t0) * 64;
        int tx = tid & 15, ty = tid >> 4;
#pragma unroll
        for (int i = 0; i < 8; i++) {
            int r = ty * 8 + i;
            int t = t0 + r;
            if (t < M) {
                float pos = inc[t] * inv_len;
#pragma unroll
                for (int j = 0; j < 4; j++) {
                    int c = tx * 4 + j;
                    int jj = c & 31;
                    float ang = pos * theta[jj];
                    float sv, cv;
                    __sincosf(ang, &sv, &cv);
                    float x1 = Cs[r][jj], x2 = Cs[r][jj + 32];
                    float v = (c < 32) ? (x1 * cv - x2 * sv) : (x1 * sv + x2 * cv);
                    outp[(size_t)r * 64 + c] = __float2bfloat16(v);
                }
            } else {
#pragma unroll
                for (int j = 0; j < 4; j++)
                    outp[(size_t)r * 64 + tx * 4 + j] = __float2bfloat16(0.f);
            }
        }
    } else {
        // V: write transposed (B,H,64,Mpad), bias already in Cs
        bf16* outp = g_Vb + (size_t)(b * NH + h) * 64 * Mpad;
        int tt = tid & 127, db = (tid >> 7) * 32;
#pragma unroll
        for (int p = 0; p < 32; p++) {
            int d = db + p;
            outp[(size_t)d * Mpad + t0 + tt] = __float2bfloat16(Cs[tt][d]);
        }
    }
}

// ---------------------------------------------------------------------------
// FA2-style attention, bf16 HMMA. CTA = 128 q-rows x (b,h). 8 warps, each
// owns 16 full q rows (row reductions stay in a lane-quad). k-tiles of 64.
// ---------------------------------------------------------------------------
__global__ void __launch_bounds__(256) attn_mma(const int* __restrict__ tmask)
{
    __shared__ bf16 Qs[128][72];
    __shared__ bf16 Ks[64][72];
    __shared__ bf16 Vs[64][72];   // (dh, key)
    __shared__ float Ms[64];

    const int qt = blockIdx.x, h = blockIdx.y, b = blockIdx.z;
    const int tid = threadIdx.x;
    const int wid = tid >> 5, lane = tid & 31;
    const int g = lane >> 2, tig = lane & 3;
    const int r0 = wid * 16;

    const bf16* Qg = g_Qb + ((size_t)(b * NH + h) * TQPAD + qt * 128) * 64;
    const bf16* Kg = g_Kb + (size_t)(b * NH + h) * TTXT * 64;
    const bf16* Vg = g_Vb + (size_t)(b * NH + h) * 64 * TTXT;

#pragma unroll
    for (int p = 0; p < 4; p++) {
        int idx = tid + p * 256;
        int r = idx >> 3, c8 = (idx & 7) * 8;
        *(uint4*)&Qs[r][c8] = *(const uint4*)&Qg[(size_t)r * 64 + c8];
    }
    __syncthreads();

    uint32_t qa[4][4];
#pragma unroll
    for (int kc = 0; kc < 4; kc++) {
        qa[kc][0] = *(const uint32_t*)&Qs[r0 + g][kc * 16 + 2 * tig];
        qa[kc][1] = *(const uint32_t*)&Qs[r0 + g + 8][kc * 16 + 2 * tig];
        qa[kc][2] = *(const uint32_t*)&Qs[r0 + g][kc * 16 + 8 + 2 * tig];
        qa[kc][3] = *(const uint32_t*)&Qs[r0 + g + 8][kc * 16 + 8 + 2 * tig];
    }

    float oc[8][4] = {};
    float m0v = -1e30f, m1v = -1e30f, l0 = 0.f, l1 = 0.f;

    for (int kt = 0; kt < TTXT / 64; kt++) {
        __syncthreads();
#pragma unroll
        for (int p = 0; p < 2; p++) {
            int idx = tid + p * 256;
            int r = idx >> 3, c8 = (idx & 7) * 8;
            *(uint4*)&Ks[r][c8] = *(const uint4*)&Kg[(size_t)(kt * 64 + r) * 64 + c8];
            *(uint4*)&Vs[r][c8] = *(const uint4*)&Vg[(size_t)r * TTXT + kt * 64 + c8];
        }
        if (tid < 64) Ms[tid] = (float)tmask[b * TTXT + kt * 64 + tid];
        __syncthreads();

        // S = Q K^T  (warp stripe 16x64)
        float sc[8][4] = {};
#pragma unroll
        for (int ns = 0; ns < 8; ns++) {
#pragma unroll
            for (int kc = 0; kc < 4; kc++) {
                uint32_t bb[2];
                bb[0] = *(const uint32_t*)&Ks[ns * 8 + g][kc * 16 + 2 * tig];
                bb[1] = *(const uint32_t*)&Ks[ns * 8 + g][kc * 16 + 8 + 2 * tig];
                mma_bf16(sc[ns], qa[kc], bb);
            }
        }

        // mask + scale, row max
        float mx0 = -1e30f, mx1 = -1e30f;
#pragma unroll
        for (int ns = 0; ns < 8; ns++) {
            float mk0 = Ms[ns * 8 + 2 * tig], mk1 = Ms[ns * 8 + 2 * tig + 1];
            sc[ns][0] = (mk0 != 0.f) ? sc[ns][0] * SCALE_ATT : -1e30f;
            sc[ns][1] = (mk1 != 0.f) ? sc[ns][1] * SCALE_ATT : -1e30f;
            sc[ns][2] = (mk0 != 0.f) ? sc[ns][2] * SCALE_ATT : -1e30f;
            sc[ns][3] = (mk1 != 0.f) ? sc[ns][3] * SCALE_ATT : -1e30f;
            mx0 = fmaxf(mx0, fmaxf(sc[ns][0], sc[ns][1]));
            mx1 = fmaxf(mx1, fmaxf(sc[ns][2], sc[ns][3]));
        }
        mx0 = fmaxf(mx0, __shfl_xor_sync(~0u, mx0, 1));
        mx0 = fmaxf(mx0, __shfl_xor_sync(~0u, mx0, 2));
        mx1 = fmaxf(mx1, __shfl_xor_sync(~0u, mx1, 1));
        mx1 = fmaxf(mx1, __shfl_xor_sync(~0u, mx1, 2));

        float mn0 = fmaxf(m0v, mx0), mn1 = fmaxf(m1v, mx1);
        float corr0 = __expf(m0v - mn0), corr1 = __expf(m1v - mn1);
        m0v = mn0; m1v = mn1;

        float rs0 = 0.f, rs1 = 0.f;
#pragma unroll
        for (int ns = 0; ns < 8; ns++) {
            // masked entries are exactly -1e30: force p = 0 (avoids all-masked-tile trap)
            float e0 = (sc[ns][0] > -1e29f) ? __expf(sc[ns][0] - mn0) : 0.f;
            float e1 = (sc[ns][1] > -1e29f) ? __expf(sc[ns][1] - mn0) : 0.f;
            float e2 = (sc[ns][2] > -1e29f) ? __expf(sc[ns][2] - mn1) : 0.f;
            float e3 = (sc[ns][3] > -1e29f) ? __expf(sc[ns][3] - mn1) : 0.f;
            rs0 += e0 + e1; rs1 += e2 + e3;
            sc[ns][0] = e0; sc[ns][1] = e1; sc[ns][2] = e2; sc[ns][3] = e3;
        }
        rs0 += __shfl_xor_sync(~0u, rs0, 1);
        rs0 += __shfl_xor_sync(~0u, rs0, 2);
        rs1 += __shfl_xor_sync(~0u, rs1, 1);
        rs1 += __shfl_xor_sync(~0u, rs1, 2);
        l0 = l0 * corr0 + rs0;
        l1 = l1 * corr1 + rs1;

        // pack P into A-fragments for PV
        uint32_t pa[4][4];
#pragma unroll
        for (int kc = 0; kc < 4; kc++) {
            pa[kc][0] = packbf2(sc[2 * kc][0], sc[2 * kc][1]);
            pa[kc][1] = packbf2(sc[2 * kc][2], sc[2 * kc][3]);
            pa[kc][2] = packbf2(sc[2 * kc + 1][0], sc[2 * kc + 1][1]);
            pa[kc][3] = packbf2(sc[2 * kc + 1][2], sc[2 * kc + 1][3]);
        }

#pragma unroll
        for (int ns = 0; ns < 8; ns++) {
            oc[ns][0] *= corr0; oc[ns][1] *= corr0;
            oc[ns][2] *= corr1; oc[ns][3] *= corr1;
        }
        // O += P V   (V^T in smem: Vs[dh][key])
#pragma unroll
        for (int ns = 0; ns < 8; ns++) {
#pragma unroll
            for (int kc = 0; kc < 4; kc++) {
                uint32_t vb[2];
                vb[0] = *(const uint32_t*)&Vs[ns * 8 + g][kc * 16 + 2 * tig];
                vb[1] = *(const uint32_t*)&Vs[ns * 8 + g][kc * 16 + 8 + 2 * tig];
                mma_bf16(oc[ns], pa[kc], vb);
            }
        }
    }

    float inv0 = 1.f / l0, inv1 = 1.f / l1;
    int tg = qt * 128 + r0 + g;
    bf16* Ob = g_Ob + (size_t)b * TQPAD * TDm + h * 64;
#pragma unroll
    for (int ns = 0; ns < 8; ns++) {
        int c = ns * 8 + 2 * tig;
        *(uint32_t*)&Ob[(size_t)tg * TDm + c] =
            packbf2(oc[ns][0] * inv0, oc[ns][1] * inv0);
        *(uint32_t*)&Ob[(size_t)(tg + 8) * TDm + c] =
            packbf2(oc[ns][2] * inv1, oc[ns][3] * inv1);
    }
}

// ---------------------------------------------------------------------------
// Output projection (bf16 HMMA) + residual + bias + mask.
// out[b,c,t] = (x[b,c,t] + bo[c] + sum_d O[b,t,d] Wo[c,d]) * lmask[b,t]
// ---------------------------------------------------------------------------
__global__ void __launch_bounds__(256) oproj_mma(
    const float* __restrict__ x, const float* __restrict__ bo,
    const float* __restrict__ lmask, float* __restrict__ out)
{
    __shared__ __align__(16) char smraw[33280];
    bf16 (*As)[72] = (bf16(*)[72])smraw;
    bf16 (*Bs)[72] = (bf16(*)[72])(smraw + 128 * 72 * 2);
    float (*Cs)[65] = (float(*)[65])smraw;

    const int b = blockIdx.z;
    const int t0 = blockIdx.x * 128;
    const int c0 = blockIdx.y * 64;
    const int tid = threadIdx.x;
    const int wid = tid >> 5, lane = tid & 31;
    const int g = lane >> 2, tig = lane & 3;
    const int m0 = (wid >> 1) * 32, n0 = (wid & 1) * 32;

    const bf16* Ab = g_Ob + ((size_t)b * TQPAD + t0) * TDm;
    const bf16* Wb = g_Wob + (size_t)c0 * TDm;

    float acc[2][4][4] = {};

    for (int k0 = 0; k0 < TDm; k0 += 64) {
#pragma unroll
        for (int p = 0; p < 4; p++) {
            int idx = tid + p * 256;
            int r = idx >> 3, c8 = (idx & 7) * 8;
            *(uint4*)&As[r][c8] = *(const uint4*)&Ab[(size_t)r * TDm + k0 + c8];
        }
#pragma unroll
        for (int p = 0; p < 2; p++) {
            int idx = tid + p * 256;
            int r = idx >> 3, c8 = (idx & 7) * 8;
            *(uint4*)&Bs[r][c8] = *(const uint4*)&Wb[(size_t)r * TDm + k0 + c8];
        }
        __syncthreads();
#pragma unroll
        for (int kc = 0; kc < 4; kc++) {
            uint32_t am[2][4];
#pragma unroll
            for (int ms = 0; ms < 2; ms++) {
                int r = m0 + ms * 16 + g;
                am[ms][0] = *(const uint32_t*)&As[r][kc * 16 + 2 * tig];
                am[ms][1] = *(const uint32_t*)&As[r + 8][kc * 16 + 2 * tig];
                am[ms][2] = *(const uint32_t*)&As[r][kc * 16 + 8 + 2 * tig];
                am[ms][3] = *(const uint32_t*)&As[r + 8][kc * 16 + 8 + 2 * tig];
            }
#pragma unroll
            for (int ns = 0; ns < 4; ns++) {
                uint32_t bb[2];
                int nr = n0 + ns * 8 + g;
                bb[0] = *(const uint32_t*)&Bs[nr][kc * 16 + 2 * tig];
                bb[1] = *(const uint32_t*)&Bs[nr][kc * 16 + 8 + 2 * tig];
                mma_bf16(acc[0][ns], am[0], bb);
                mma_bf16(acc[1][ns], am[1], bb);
            }
        }
        __syncthreads();
    }

#pragma unroll
    for (int ms = 0; ms < 2; ms++)
#pragma unroll
        for (int ns = 0; ns < 4; ns++) {
            int r = m0 + ms * 16 + g;
            int c = n0 + ns * 8 + 2 * tig;
            Cs[r][c]         = acc[ms][ns][0];
            Cs[r][c + 1]     = acc[ms][ns][1];
            Cs[r + 8][c]     = acc[ms][ns][2];
            Cs[r + 8][c + 1] = acc[ms][ns][3];
        }
    __syncthreads();

    int tt = tid & 127;
    int t = t0 + tt;
    if (t < TLAT) {
        float lm = lmask[(size_t)b * TLAT + t];
        int cb = (tid >> 7) * 32;
#pragma unroll
        for (int p = 0; p < 32; p++) {
            int cc = cb + p;
            int c = c0 + cc;
            size_t idx = ((size_t)b * CHN + c) * TLAT + t;
            out[idx] = (x[idx] + bo[c] + Cs[tt][cc]) * lm;
        }
    }
}

// ---------------------------------------------------------------------------
extern "C" void kernel_launch(void* const* d_in, const int* in_sizes, int n_in,
                              void* d_out, int out_size)
{
    const float* x     = (const float*)d_in[0];
    const float* temb  = (const float*)d_in[1];
    const float* lmask = (const float*)d_in[2];
    const int*   tmask = (const int*)d_in[3];
    const float* Wq    = (const float*)d_in[4];
    const float* bq    = (const float*)d_in[5];
    const float* Wk    = (const float*)d_in[6];
    const float* bk    = (const float*)d_in[7];
    const float* Wv    = (const float*)d_in[8];
    const float* bv    = (const float*)d_in[9];
    const float* Wo    = (const float*)d_in[10];
    const float* bo    = (const float*)d_in[11];
    const float* theta = (const float*)d_in[12];
    const float* inc   = (const float*)d_in[13];
    float* out = (float*)d_out;

    // transpose + bf16 convert inputs
    transpose_bf<<<dim3(TQPAD / 32, CHN / 32, Bsz), dim3(32, 8)>>>(
        x, CHN, TLAT, TQPAD, 0);
    transpose_bf<<<dim3(TTXT / 32, TDm / 32, Bsz), dim3(32, 8)>>>(
        temb, TDm, TTXT, TTXT, 1);
    conv_weights<<<(TDm * CHN + 255) / 256, 256>>>(Wq, Wk, Wv, Wo);

    // projections (+bias, +RoPE)
    proj_mma<<<dim3(TQPAD / 128, NH, Bsz), 256>>>(bq, theta, inc,
                                                  TQPAD, TLAT, CHN,
                                                  1.f / (float)TLAT, 0);
    proj_mma<<<dim3(TTXT / 128, NH, Bsz), 256>>>(bk, theta, inc,
                                                 TTXT, TTXT, TDm,
                                                 1.f / (float)TTXT, 1);
    proj_mma<<<dim3(TTXT / 128, NH, Bsz), 256>>>(bv, theta, inc,
                                                 TTXT, TTXT, TDm,
                                                 1.f / (float)TTXT, 2);

    // attention
    attn_mma<<<dim3(TQPAD / 128, NH, Bsz), 256>>>(tmask);

    // output projection + residual + mask
    oproj_mma<<<dim3(TQPAD / 128, CHN / 64, Bsz), 256>>>(x, bo, lmask, out);
}

// round 3
// speedup vs baseline: 6.0648x; 1.0217x over previous
#include <cuda_runtime.h>
#include <cuda_bf16.h>
#include <math.h>
#include <stdint.h>

typedef __nv_bfloat16 bf16;

#define Bsz 64
#define CHN 512
#define TDm 256
#define NH 4
#define DHd 64
#define TLAT 1000
#define TQPAD 1024
#define TTXT 512
#define SCALE_ATT 0.0625f

// ---------------- scratch (device globals; allocation-free) ----------------
__device__ bf16 g_xT[(size_t)Bsz * TQPAD * CHN];      // (B,1024,512) x transposed
__device__ bf16 g_tT[(size_t)Bsz * TTXT * TDm];       // (B,512,256)  temb transposed
__device__ bf16 g_Qb[(size_t)Bsz * NH * TQPAD * DHd]; // (B,H,1024,64) rope'd
__device__ bf16 g_Kb[(size_t)Bsz * NH * TTXT * DHd];  // (B,H,512,64) rope'd
__device__ bf16 g_Vb[(size_t)Bsz * NH * DHd * TTXT];  // (B,H,64,512) transposed
__device__ bf16 g_Ob[(size_t)Bsz * TQPAD * TDm];      // (B,1024,256) attn out
__device__ bf16 g_Wqb[TDm * CHN];
__device__ bf16 g_Wkb[TDm * TDm];
__device__ bf16 g_Wvb[TDm * TDm];
__device__ bf16 g_Wob[CHN * TDm];

// ---------------------------------------------------------------------------
__device__ __forceinline__ void mma_bf16(float c[4], const uint32_t a[4],
                                         const uint32_t b[2]) {
    asm volatile(
        "mma.sync.aligned.m16n8k16.row.col.f32.bf16.bf16.f32 "
        "{%0,%1,%2,%3}, {%4,%5,%6,%7}, {%8,%9}, {%0,%1,%2,%3};\n"
        : "+f"(c[0]), "+f"(c[1]), "+f"(c[2]), "+f"(c[3])
        : "r"(a[0]), "r"(a[1]), "r"(a[2]), "r"(a[3]), "r"(b[0]), "r"(b[1]));
}

__device__ __forceinline__ uint32_t packbf2(float lo, float hi) {
    uint32_t r;
    asm("cvt.rn.bf16x2.f32 %0, %1, %2;" : "=r"(r) : "f"(hi), "f"(lo));
    return r;
}

__device__ __forceinline__ void ldsm_x4(uint32_t r[4], const bf16* p) {
    uint32_t a = (uint32_t)__cvta_generic_to_shared(p);
    asm volatile(
        "ldmatrix.sync.aligned.m8n8.x4.shared.b16 {%0,%1,%2,%3}, [%4];"
        : "=r"(r[0]), "=r"(r[1]), "=r"(r[2]), "=r"(r[3]) : "r"(a));
}

// ---------------------------------------------------------------------------
// transpose+convert: in (B,D1,D2) f32 -> out (B,D2pad,D1) bf16; dst 0=g_xT 1=g_tT
// ---------------------------------------------------------------------------
__global__ void __launch_bounds__(256) transpose_bf(
    const float* __restrict__ in, int D1, int D2, int D2pad, int dst)
{
    __shared__ float tile[32][33];
    const int b = blockIdx.z;
    const int j0 = blockIdx.x * 32;   // D2
    const int i0 = blockIdx.y * 32;   // D1
    const int tx = threadIdx.x, ty = threadIdx.y;  // (32, 8)
    const float* inb = in + (size_t)b * D1 * D2;
#pragma unroll
    for (int p = 0; p < 4; p++) {
        int r = i0 + ty + p * 8;
        int j = j0 + tx;
        tile[ty + p * 8][tx] = (j < D2) ? inb[(size_t)r * D2 + j] : 0.f;
    }
    __syncthreads();
    bf16* out = (dst == 0) ? g_xT : g_tT;
    bf16* outb = out + (size_t)b * D2pad * D1;
#pragma unroll
    for (int p = 0; p < 4; p++) {
        int j = j0 + ty + p * 8;
        outb[(size_t)j * D1 + i0 + tx] = __float2bfloat16(tile[tx][ty + p * 8]);
    }
}

// ---------------------------------------------------------------------------
__global__ void __launch_bounds__(256) conv_weights(
    const float* __restrict__ Wq, const float* __restrict__ Wk,
    const float* __restrict__ Wv, const float* __restrict__ Wo)
{
    int i = blockIdx.x * 256 + threadIdx.x;
    if (i < TDm * CHN) g_Wqb[i] = __float2bfloat16(Wq[i]);
    if (i < TDm * TDm) {
        g_Wkb[i] = __float2bfloat16(Wk[i]);
        g_Wvb[i] = __float2bfloat16(Wv[i]);
    }
    if (i < CHN * TDm) g_Wob[i] = __float2bfloat16(Wo[i]);
}

// ---------------------------------------------------------------------------
// Projection GEMM (bf16 HMMA + ldmatrix): C[t,d] = A[t,:].W[d,:] + bias, RoPE.
// CTA tile 128(M=t) x 64(N=d, one head). 8 warps: warp tile 32x32.
// mode: 0=Q(rope, g_Qb) 1=K(rope, g_Kb) 2=V(no rope, g_Vb transposed)
// ---------------------------------------------------------------------------
__global__ void __launch_bounds__(256) proj_mma(
    const float* __restrict__ bias, const float* __restrict__ theta,
    const float* __restrict__ inc, int Mpad, int M, int Kdim,
    float inv_len, int mode)
{
    __shared__ __align__(16) char smraw[33280];
    bf16 (*As)[72] = (bf16(*)[72])smraw;                   // 128x72 = 18432 B
    bf16 (*Bs)[72] = (bf16(*)[72])(smraw + 128 * 72 * 2);  //  64x72 =  9216 B
    float (*Cs)[65] = (float(*)[65])smraw;                 // 128x65 = 33280 B

    const int b = blockIdx.z, h = blockIdx.y;
    const int t0 = blockIdx.x * 128;
    const int tid = threadIdx.x;
    const int wid = tid >> 5, lane = tid & 31;
    const int g = lane >> 2, tig = lane & 3;
    const int m0 = (wid >> 1) * 32, n0 = (wid & 1) * 32;

    // ldmatrix per-lane address offsets
    const int a_row = (lane & 7) + ((lane >> 3) & 1) * 8;
    const int a_col = (lane >> 4) * 8;
    const int b_row = ((lane >> 4) & 1) * 8 + (lane & 7);
    const int b_col = ((lane >> 3) & 1) * 8;

    const bf16* A = (mode == 0) ? g_xT : g_tT;
    const bf16* W = (mode == 0) ? g_Wqb : (mode == 1) ? g_Wkb : g_Wvb;
    const bf16* Ab = A + ((size_t)b * Mpad + t0) * Kdim;
    const bf16* Wb = W + (size_t)(h * 64) * Kdim;

    float acc[2][4][4] = {};

    for (int k0 = 0; k0 < Kdim; k0 += 64) {
#pragma unroll
        for (int p = 0; p < 4; p++) {
            int idx = tid + p * 256;
            int r = idx >> 3, c8 = (idx & 7) * 8;
            *(uint4*)&As[r][c8] = *(const uint4*)&Ab[(size_t)r * Kdim + k0 + c8];
        }
#pragma unroll
        for (int p = 0; p < 2; p++) {
            int idx = tid + p * 256;
            int r = idx >> 3, c8 = (idx & 7) * 8;
            *(uint4*)&Bs[r][c8] = *(const uint4*)&Wb[(size_t)r * Kdim + k0 + c8];
        }
        __syncthreads();
#pragma unroll
        for (int kc = 0; kc < 4; kc++) {
            uint32_t am[2][4];
            ldsm_x4(am[0], &As[m0 + a_row][kc * 16 + a_col]);
            ldsm_x4(am[1], &As[m0 + 16 + a_row][kc * 16 + a_col]);
#pragma unroll
            for (int np = 0; np < 2; np++) {
                uint32_t bb[4];
                ldsm_x4(bb, &Bs[n0 + np * 16 + b_row][kc * 16 + b_col]);
                mma_bf16(acc[0][2 * np], am[0], bb);
                mma_bf16(acc[0][2 * np + 1], am[0], bb + 2);
                mma_bf16(acc[1][2 * np], am[1], bb);
                mma_bf16(acc[1][2 * np + 1], am[1], bb + 2);
            }
        }
        __syncthreads();
    }

    // stage to smem with bias (pre-RoPE, matching reference)
#pragma unroll
    for (int ms = 0; ms < 2; ms++)
#pragma unroll
        for (int ns = 0; ns < 4; ns++) {
            int r = m0 + ms * 16 + g;
            int c = n0 + ns * 8 + 2 * tig;
            float bv0 = bias[h * 64 + c], bv1 = bias[h * 64 + c + 1];
            Cs[r][c]         = acc[ms][ns][0] + bv0;
            Cs[r][c + 1]     = acc[ms][ns][1] + bv1;
            Cs[r + 8][c]     = acc[ms][ns][2] + bv0;
            Cs[r + 8][c + 1] = acc[ms][ns][3] + bv1;
        }
    __syncthreads();

    if (mode < 2) {
        bf16* outp = ((mode == 0) ? g_Qb : g_Kb) +
                     ((size_t)(b * NH + h) * Mpad + t0) * 64;
        int tx = tid & 15, ty = tid >> 4;
#pragma unroll
        for (int i = 0; i < 8; i++) {
            int r = ty * 8 + i;
            int t = t0 + r;
            if (t < M) {
                float pos = inc[t] * inv_len;
#pragma unroll
                for (int j = 0; j < 4; j++) {
                    int c = tx * 4 + j;
                    int jj = c & 31;
                    float ang = pos * theta[jj];
                    float sv, cv;
                    __sincosf(ang, &sv, &cv);
                    float x1 = Cs[r][jj], x2 = Cs[r][jj + 32];
                    float v = (c < 32) ? (x1 * cv - x2 * sv) : (x1 * sv + x2 * cv);
                    outp[(size_t)r * 64 + c] = __float2bfloat16(v);
                }
            } else {
#pragma unroll
                for (int j = 0; j < 4; j++)
                    outp[(size_t)r * 64 + tx * 4 + j] = __float2bfloat16(0.f);
            }
        }
    } else {
        // V: write transposed (B,H,64,Mpad), bias already in Cs
        bf16* outp = g_Vb + (size_t)(b * NH + h) * 64 * Mpad;
        int tt = tid & 127, db = (tid >> 7) * 32;
#pragma unroll
        for (int p = 0; p < 32; p++) {
            int d = db + p;
            outp[(size_t)d * Mpad + t0 + tt] = __float2bfloat16(Cs[tt][d]);
        }
    }
}

// ---------------------------------------------------------------------------
// FA2-style attention, bf16 HMMA + ldmatrix. CTA = 128 q-rows x (b,h).
// 8 warps, each owns 16 full q rows. k-tiles of 64.
// ---------------------------------------------------------------------------
__global__ void __launch_bounds__(256) attn_mma(const int* __restrict__ tmask)
{
    __shared__ __align__(16) bf16 Qs[128][72];
    __shared__ __align__(16) bf16 Ks[64][72];
    __shared__ __align__(16) bf16 Vs[64][72];   // (dh, key)
    __shared__ float Ms[64];

    const int qt = blockIdx.x, h = blockIdx.y, b = blockIdx.z;
    const int tid = threadIdx.x;
    const int wid = tid >> 5, lane = tid & 31;
    const int g = lane >> 2, tig = lane & 3;
    const int r0 = wid * 16;

    const int a_row = (lane & 7) + ((lane >> 3) & 1) * 8;
    const int a_col = (lane >> 4) * 8;
    const int b_row = ((lane >> 4) & 1) * 8 + (lane & 7);
    const int b_col = ((lane >> 3) & 1) * 8;

    const bf16* Qg = g_Qb + ((size_t)(b * NH + h) * TQPAD + qt * 128) * 64;
    const bf16* Kg = g_Kb + (size_t)(b * NH + h) * TTXT * 64;
    const bf16* Vg = g_Vb + (size_t)(b * NH + h) * 64 * TTXT;

#pragma unroll
    for (int p = 0; p < 4; p++) {
        int idx = tid + p * 256;
        int r = idx >> 3, c8 = (idx & 7) * 8;
        *(uint4*)&Qs[r][c8] = *(const uint4*)&Qg[(size_t)r * 64 + c8];
    }
    __syncthreads();

    uint32_t qa[4][4];
#pragma unroll
    for (int kc = 0; kc < 4; kc++)
        ldsm_x4(qa[kc], &Qs[r0 + a_row][kc * 16 + a_col]);

    float oc[8][4] = {};
    float m0v = -1e30f, m1v = -1e30f, l0 = 0.f, l1 = 0.f;

    for (int kt = 0; kt < TTXT / 64; kt++) {
        __syncthreads();
#pragma unroll
        for (int p = 0; p < 2; p++) {
            int idx = tid + p * 256;
            int r = idx >> 3, c8 = (idx & 7) * 8;
            *(uint4*)&Ks[r][c8] = *(const uint4*)&Kg[(size_t)(kt * 64 + r) * 64 + c8];
            *(uint4*)&Vs[r][c8] = *(const uint4*)&Vg[(size_t)r * TTXT + kt * 64 + c8];
        }
        if (tid < 64) Ms[tid] = (float)tmask[b * TTXT + kt * 64 + tid];
        __syncthreads();

        // S = Q K^T  (warp stripe 16x64)
        float sc[8][4] = {};
#pragma unroll
        for (int kc = 0; kc < 4; kc++) {
#pragma unroll
            for (int np = 0; np < 4; np++) {
                uint32_t bb[4];
                ldsm_x4(bb, &Ks[np * 16 + b_row][kc * 16 + b_col]);
                mma_bf16(sc[2 * np], qa[kc], bb);
                mma_bf16(sc[2 * np + 1], qa[kc], bb + 2);
            }
        }

        // mask + scale, row max
        float mx0 = -1e30f, mx1 = -1e30f;
#pragma unroll
        for (int ns = 0; ns < 8; ns++) {
            float mk0 = Ms[ns * 8 + 2 * tig], mk1 = Ms[ns * 8 + 2 * tig + 1];
            sc[ns][0] = (mk0 != 0.f) ? sc[ns][0] * SCALE_ATT : -1e30f;
            sc[ns][1] = (mk1 != 0.f) ? sc[ns][1] * SCALE_ATT : -1e30f;
            sc[ns][2] = (mk0 != 0.f) ? sc[ns][2] * SCALE_ATT : -1e30f;
            sc[ns][3] = (mk1 != 0.f) ? sc[ns][3] * SCALE_ATT : -1e30f;
            mx0 = fmaxf(mx0, fmaxf(sc[ns][0], sc[ns][1]));
            mx1 = fmaxf(mx1, fmaxf(sc[ns][2], sc[ns][3]));
        }
        mx0 = fmaxf(mx0, __shfl_xor_sync(~0u, mx0, 1));
        mx0 = fmaxf(mx0, __shfl_xor_sync(~0u, mx0, 2));
        mx1 = fmaxf(mx1, __shfl_xor_sync(~0u, mx1, 1));
        mx1 = fmaxf(mx1, __shfl_xor_sync(~0u, mx1, 2));

        float mn0 = fmaxf(m0v, mx0), mn1 = fmaxf(m1v, mx1);
        float corr0 = __expf(m0v - mn0), corr1 = __expf(m1v - mn1);
        m0v = mn0; m1v = mn1;

        float rs0 = 0.f, rs1 = 0.f;
#pragma unroll
        for (int ns = 0; ns < 8; ns++) {
            // masked entries are exactly -1e30: force p = 0
            float e0 = (sc[ns][0] > -1e29f) ? __expf(sc[ns][0] - mn0) : 0.f;
            float e1 = (sc[ns][1] > -1e29f) ? __expf(sc[ns][1] - mn0) : 0.f;
            float e2 = (sc[ns][2] > -1e29f) ? __expf(sc[ns][2] - mn1) : 0.f;
            float e3 = (sc[ns][3] > -1e29f) ? __expf(sc[ns][3] - mn1) : 0.f;
            rs0 += e0 + e1; rs1 += e2 + e3;
            sc[ns][0] = e0; sc[ns][1] = e1; sc[ns][2] = e2; sc[ns][3] = e3;
        }
        rs0 += __shfl_xor_sync(~0u, rs0, 1);
        rs0 += __shfl_xor_sync(~0u, rs0, 2);
        rs1 += __shfl_xor_sync(~0u, rs1, 1);
        rs1 += __shfl_xor_sync(~0u, rs1, 2);
        l0 = l0 * corr0 + rs0;
        l1 = l1 * corr1 + rs1;

        // pack P into A-fragments for PV
        uint32_t pa[4][4];
#pragma unroll
        for (int kc = 0; kc < 4; kc++) {
            pa[kc][0] = packbf2(sc[2 * kc][0], sc[2 * kc][1]);
            pa[kc][1] = packbf2(sc[2 * kc][2], sc[2 * kc][3]);
            pa[kc][2] = packbf2(sc[2 * kc + 1][0], sc[2 * kc + 1][1]);
            pa[kc][3] = packbf2(sc[2 * kc + 1][2], sc[2 * kc + 1][3]);
        }

#pragma unroll
        for (int ns = 0; ns < 8; ns++) {
            oc[ns][0] *= corr0; oc[ns][1] *= corr0;
            oc[ns][2] *= corr1; oc[ns][3] *= corr1;
        }
        // O += P V   (V^T in smem: Vs[dh][key])
#pragma unroll
        for (int kc = 0; kc < 4; kc++) {
#pragma unroll
            for (int np = 0; np < 4; np++) {
                uint32_t vb[4];
                ldsm_x4(vb, &Vs[np * 16 + b_row][kc * 16 + b_col]);
                mma_bf16(oc[2 * np], pa[kc], vb);
                mma_bf16(oc[2 * np + 1], pa[kc], vb + 2);
            }
        }
    }

    float inv0 = 1.f / l0, inv1 = 1.f / l1;
    int tg = qt * 128 + r0 + g;
    bf16* Ob = g_Ob + (size_t)b * TQPAD * TDm + h * 64;
#pragma unroll
    for (int ns = 0; ns < 8; ns++) {
        int c = ns * 8 + 2 * tig;
        *(uint32_t*)&Ob[(size_t)tg * TDm + c] =
            packbf2(oc[ns][0] * inv0, oc[ns][1] * inv0);
        *(uint32_t*)&Ob[(size_t)(tg + 8) * TDm + c] =
            packbf2(oc[ns][2] * inv1, oc[ns][3] * inv1);
    }
}

// ---------------------------------------------------------------------------
// Output projection (bf16 HMMA + ldmatrix) + residual + bias + mask.
// out[b,c,t] = (x[b,c,t] + bo[c] + sum_d O[b,t,d] Wo[c,d]) * lmask[b,t]
// ---------------------------------------------------------------------------
__global__ void __launch_bounds__(256) oproj_mma(
    const float* __restrict__ x, const float* __restrict__ bo,
    const float* __restrict__ lmask, float* __restrict__ out)
{
    __shared__ __align__(16) char smraw[33280];
    bf16 (*As)[72] = (bf16(*)[72])smraw;
    bf16 (*Bs)[72] = (bf16(*)[72])(smraw + 128 * 72 * 2);
    float (*Cs)[65] = (float(*)[65])smraw;

    const int b = blockIdx.z;
    const int t0 = blockIdx.x * 128;
    const int c0 = blockIdx.y * 64;
    const int tid = threadIdx.x;
    const int wid = tid >> 5, lane = tid & 31;
    const int g = lane >> 2, tig = lane & 3;
    const int m0 = (wid >> 1) * 32, n0 = (wid & 1) * 32;

    const int a_row = (lane & 7) + ((lane >> 3) & 1) * 8;
    const int a_col = (lane >> 4) * 8;
    const int b_row = ((lane >> 4) & 1) * 8 + (lane & 7);
    const int b_col = ((lane >> 3) & 1) * 8;

    const bf16* Ab = g_Ob + ((size_t)b * TQPAD + t0) * TDm;
    const bf16* Wb = g_Wob + (size_t)c0 * TDm;

    float acc[2][4][4] = {};

    for (int k0 = 0; k0 < TDm; k0 += 64) {
#pragma unroll
        for (int p = 0; p < 4; p++) {
            int idx = tid + p * 256;
            int r = idx >> 3, c8 = (idx & 7) * 8;
            *(uint4*)&As[r][c8] = *(const uint4*)&Ab[(size_t)r * TDm + k0 + c8];
        }
#pragma unroll
        for (int p = 0; p < 2; p++) {
            int idx = tid + p * 256;
            int r = idx >> 3, c8 = (idx & 7) * 8;
            *(uint4*)&Bs[r][c8] = *(const uint4*)&Wb[(size_t)r * TDm + k0 + c8];
        }
        __syncthreads();
#pragma unroll
        for (int kc = 0; kc < 4; kc++) {
            uint32_t am[2][4];
            ldsm_x4(am[0], &As[m0 + a_row][kc * 16 + a_col]);
            ldsm_x4(am[1], &As[m0 + 16 + a_row][kc * 16 + a_col]);
#pragma unroll
            for (int np = 0; np < 2; np++) {
                uint32_t bb[4];
                ldsm_x4(bb, &Bs[n0 + np * 16 + b_row][kc * 16 + b_col]);
                mma_bf16(acc[0][2 * np], am[0], bb);
                mma_bf16(acc[0][2 * np + 1], am[0], bb + 2);
                mma_bf16(acc[1][2 * np], am[1], bb);
                mma_bf16(acc[1][2 * np + 1], am[1], bb + 2);
            }
        }
        __syncthreads();
    }

#pragma unroll
    for (int ms = 0; ms < 2; ms++)
#pragma unroll
        for (int ns = 0; ns < 4; ns++) {
            int r = m0 + ms * 16 + g;
            int c = n0 + ns * 8 + 2 * tig;
            Cs[r][c]         = acc[ms][ns][0];
            Cs[r][c + 1]     = acc[ms][ns][1];
            Cs[r + 8][c]     = acc[ms][ns][2];
            Cs[r + 8][c + 1] = acc[ms][ns][3];
        }
    __syncthreads();

    int tt = tid & 127;
    int t = t0 + tt;
    if (t < TLAT) {
        float lm = lmask[(size_t)b * TLAT + t];
        int cb = (tid >> 7) * 32;
#pragma unroll
        for (int p = 0; p < 32; p++) {
            int cc = cb + p;
            int c = c0 + cc;
            size_t idx = ((size_t)b * CHN + c) * TLAT + t;
            out[idx] = (x[idx] + bo[c] + Cs[tt][cc]) * lm;
        }
    }
}

// ---------------------------------------------------------------------------
extern "C" void kernel_launch(void* const* d_in, const int* in_sizes, int n_in,
                              void* d_out, int out_size)
{
    const float* x     = (const float*)d_in[0];
    const float* temb  = (const float*)d_in[1];
    const float* lmask = (const float*)d_in[2];
    const int*   tmask = (const int*)d_in[3];
    const float* Wq    = (const float*)d_in[4];
    const float* bq    = (const float*)d_in[5];
    const float* Wk    = (const float*)d_in[6];
    const float* bk    = (const float*)d_in[7];
    const float* Wv    = (const float*)d_in[8];
    const float* bv    = (const float*)d_in[9];
    const float* Wo    = (const float*)d_in[10];
    const float* bo    = (const float*)d_in[11];
    const float* theta = (const float*)d_in[12];
    const float* inc   = (const float*)d_in[13];
    float* out = (float*)d_out;

    // transpose + bf16 convert inputs
    transpose_bf<<<dim3(TQPAD / 32, CHN / 32, Bsz), dim3(32, 8)>>>(
        x, CHN, TLAT, TQPAD, 0);
    transpose_bf<<<dim3(TTXT / 32, TDm / 32, Bsz), dim3(32, 8)>>>(
        temb, TDm, TTXT, TTXT, 1);
    conv_weights<<<(TDm * CHN + 255) / 256, 256>>>(Wq, Wk, Wv, Wo);

    // projections (+bias, +RoPE)
    proj_mma<<<dim3(TQPAD / 128, NH, Bsz), 256>>>(bq, theta, inc,
                                                  TQPAD, TLAT, CHN,
                                                  1.f / (float)TLAT, 0);
    proj_mma<<<dim3(TTXT / 128, NH, Bsz), 256>>>(bk, theta, inc,
                                                 TTXT, TTXT, TDm,
                                                 1.f / (float)TTXT, 1);
    proj_mma<<<dim3(TTXT / 128, NH, Bsz), 256>>>(bv, theta, inc,
                                                 TTXT, TTXT, TDm,
                                                 1.f / (float)TTXT, 2);

    // attention
    attn_mma<<<dim3(TQPAD / 128, NH, Bsz), 256>>>(tmask);

    // output projection + residual + mask
    oproj_mma<<<dim3(TQPAD / 128, CHN / 64, Bsz), 256>>>(x, bo, lmask, out);
}

// round 5
// speedup vs baseline: 6.5171x; 1.0746x over previous
#include <cuda_runtime.h>
#include <cuda_bf16.h>
#include <math.h>
#include <stdint.h>

typedef __nv_bfloat16 bf16;

#define Bsz 64
#define CHN 512
#define TDm 256
#define NH 4
#define DHd 64
#define TLAT 1000
#define TQPAD 1024
#define TTXT 512
#define SCALE_ATT 0.0625f

// ---------------- scratch (device globals; allocation-free) ----------------
__device__ bf16 g_xT[(size_t)Bsz * TQPAD * CHN];
__device__ bf16 g_tT[(size_t)Bsz * TTXT * TDm];
__device__ bf16 g_Qb[(size_t)Bsz * NH * TQPAD * DHd];
__device__ bf16 g_Kb[(size_t)Bsz * NH * TTXT * DHd];
__device__ bf16 g_Vb[(size_t)Bsz * NH * DHd * TTXT];
__device__ bf16 g_Ob[(size_t)Bsz * TQPAD * TDm];
__device__ bf16 g_Wqb[TDm * CHN];
__device__ bf16 g_Wkb[TDm * TDm];
__device__ bf16 g_Wvb[TDm * TDm];
__device__ bf16 g_Wob[CHN * TDm];

// ---------------------------------------------------------------------------
__device__ __forceinline__ void mma_bf16(float c[4], const uint32_t a[4],
                                         const uint32_t b[2]) {
    asm volatile(
        "mma.sync.aligned.m16n8k16.row.col.f32.bf16.bf16.f32 "
        "{%0,%1,%2,%3}, {%4,%5,%6,%7}, {%8,%9}, {%0,%1,%2,%3};\n"
        : "+f"(c[0]), "+f"(c[1]), "+f"(c[2]), "+f"(c[3])
        : "r"(a[0]), "r"(a[1]), "r"(a[2]), "r"(a[3]), "r"(b[0]), "r"(b[1]));
}

__device__ __forceinline__ uint32_t packbf2(float lo, float hi) {
    uint32_t r;
    asm("cvt.rn.bf16x2.f32 %0, %1, %2;" : "=r"(r) : "f"(hi), "f"(lo));
    return r;
}

__device__ __forceinline__ void ldsm_x4(uint32_t r[4], const bf16* p) {
    uint32_t a = (uint32_t)__cvta_generic_to_shared(p);
    asm volatile(
        "ldmatrix.sync.aligned.m8n8.x4.shared.b16 {%0,%1,%2,%3}, [%4];"
        : "=r"(r[0]), "=r"(r[1]), "=r"(r[2]), "=r"(r[3]) : "r"(a));
}

__device__ __forceinline__ void cp_async16(bf16* dst, const bf16* src) {
    uint32_t d = (uint32_t)__cvta_generic_to_shared(dst);
    asm volatile("cp.async.ca.shared.global [%0], [%1], 16;" :: "r"(d), "l"(src));
}
__device__ __forceinline__ void cp_commit() {
    asm volatile("cp.async.commit_group;");
}
template <int N>
__device__ __forceinline__ void cp_wait() {
    asm volatile("cp.async.wait_group %0;" :: "n"(N));
}

// ---------------------------------------------------------------------------
__global__ void __launch_bounds__(256) transpose_bf(
    const float* __restrict__ in, int D1, int D2, int D2pad, int dst)
{
    __shared__ float tile[32][33];
    const int b = blockIdx.z;
    const int j0 = blockIdx.x * 32;
    const int i0 = blockIdx.y * 32;
    const int tx = threadIdx.x, ty = threadIdx.y;
    const float* inb = in + (size_t)b * D1 * D2;
#pragma unroll
    for (int p = 0; p < 4; p++) {
        int r = i0 + ty + p * 8;
        int j = j0 + tx;
        tile[ty + p * 8][tx] = (j < D2) ? inb[(size_t)r * D2 + j] : 0.f;
    }
    __syncthreads();
    bf16* out = (dst == 0) ? g_xT : g_tT;
    bf16* outb = out + (size_t)b * D2pad * D1;
#pragma unroll
    for (int p = 0; p < 4; p++) {
        int j = j0 + ty + p * 8;
        outb[(size_t)j * D1 + i0 + tx] = __float2bfloat16(tile[tx][ty + p * 8]);
    }
}

// ---------------------------------------------------------------------------
__global__ void __launch_bounds__(256) conv_weights(
    const float* __restrict__ Wq, const float* __restrict__ Wk,
    const float* __restrict__ Wv, const float* __restrict__ Wo)
{
    int i = blockIdx.x * 256 + threadIdx.x;
    if (i < TDm * CHN) g_Wqb[i] = __float2bfloat16(Wq[i]);
    if (i < TDm * TDm) {
        g_Wkb[i] = __float2bfloat16(Wk[i]);
        g_Wvb[i] = __float2bfloat16(Wv[i]);
    }
    if (i < CHN * TDm) g_Wob[i] = __float2bfloat16(Wo[i]);
}

// ---------------------------------------------------------------------------
// Projection GEMM, cp.async 2-stage pipeline.
// dyn smem: As[2][128][72] @0 (36864B), Bs[2][64][72] @36864 (18432B) = 55296B
// Cs (128x65 f32, 33280B) overlays As after compute.
// ---------------------------------------------------------------------------
__global__ void __launch_bounds__(256) proj_mma(
    const float* __restrict__ bias, const float* __restrict__ theta,
    const float* __restrict__ inc, int Mpad, int M, int Kdim,
    float inv_len, int mode)
{
    extern __shared__ __align__(16) char smraw[];
    bf16 (*As)[128][72] = (bf16(*)[128][72])smraw;
    bf16 (*Bs)[64][72]  = (bf16(*)[64][72])(smraw + 2 * 128 * 72 * 2);
    float (*Cs)[65]     = (float(*)[65])smraw;

    const int b = blockIdx.z, h = blockIdx.y;
    const int t0 = blockIdx.x * 128;
    const int tid = threadIdx.x;
    const int wid = tid >> 5, lane = tid & 31;
    const int g = lane >> 2, tig = lane & 3;
    const int m0 = (wid >> 1) * 32, n0 = (wid & 1) * 32;

    const int a_row = (lane & 7) + ((lane >> 3) & 1) * 8;
    const int a_col = (lane >> 4) * 8;
    const int b_row = ((lane >> 4) & 1) * 8 + (lane & 7);
    const int b_col = ((lane >> 3) & 1) * 8;

    const bf16* A = (mode == 0) ? g_xT : g_tT;
    const bf16* W = (mode == 0) ? g_Wqb : (mode == 1) ? g_Wkb : g_Wvb;
    const bf16* Ab = A + ((size_t)b * Mpad + t0) * Kdim;
    const bf16* Wb = W + (size_t)(h * 64) * Kdim;

    const int ar = tid >> 3, ac8 = (tid & 7) * 8;   // A: 4 chunks of 32 rows
    const int KT = Kdim >> 6;

    // prologue: stage 0
#pragma unroll
    for (int p = 0; p < 4; p++)
        cp_async16(&As[0][ar + p * 32][ac8], &Ab[(size_t)(ar + p * 32) * Kdim + ac8]);
#pragma unroll
    for (int p = 0; p < 2; p++)
        cp_async16(&Bs[0][ar + p * 32][ac8], &Wb[(size_t)(ar + p * 32) * Kdim + ac8]);
    cp_commit();

    float acc[2][4][4] = {};

    for (int kt = 0; kt < KT; kt++) {
        int cur = kt & 1;
        if (kt + 1 < KT) {
            int nxt = cur ^ 1;
            int k0 = (kt + 1) << 6;
#pragma unroll
            for (int p = 0; p < 4; p++)
                cp_async16(&As[nxt][ar + p * 32][ac8],
                           &Ab[(size_t)(ar + p * 32) * Kdim + k0 + ac8]);
#pragma unroll
            for (int p = 0; p < 2; p++)
                cp_async16(&Bs[nxt][ar + p * 32][ac8],
                           &Wb[(size_t)(ar + p * 32) * Kdim + k0 + ac8]);
            cp_commit();
            cp_wait<1>();
        } else {
            cp_wait<0>();
        }
        __syncthreads();

#pragma unroll
        for (int kc = 0; kc < 4; kc++) {
            uint32_t am[2][4];
            ldsm_x4(am[0], &As[cur][m0 + a_row][kc * 16 + a_col]);
            ldsm_x4(am[1], &As[cur][m0 + 16 + a_row][kc * 16 + a_col]);
#pragma unroll
            for (int np = 0; np < 2; np++) {
                uint32_t bb[4];
                ldsm_x4(bb, &Bs[cur][n0 + np * 16 + b_row][kc * 16 + b_col]);
                mma_bf16(acc[0][2 * np], am[0], bb);
                mma_bf16(acc[0][2 * np + 1], am[0], bb + 2);
                mma_bf16(acc[1][2 * np], am[1], bb);
                mma_bf16(acc[1][2 * np + 1], am[1], bb + 2);
            }
        }
        __syncthreads();
    }

    // stage to smem with bias (pre-RoPE)
#pragma unroll
    for (int ms = 0; ms < 2; ms++)
#pragma unroll
        for (int ns = 0; ns < 4; ns++) {
            int r = m0 + ms * 16 + g;
            int c = n0 + ns * 8 + 2 * tig;
            float bv0 = bias[h * 64 + c], bv1 = bias[h * 64 + c + 1];
            Cs[r][c]         = acc[ms][ns][0] + bv0;
            Cs[r][c + 1]     = acc[ms][ns][1] + bv1;
            Cs[r + 8][c]     = acc[ms][ns][2] + bv0;
            Cs[r + 8][c + 1] = acc[ms][ns][3] + bv1;
        }
    __syncthreads();

    if (mode < 2) {
        bf16* outp = ((mode == 0) ? g_Qb : g_Kb) +
                     ((size_t)(b * NH + h) * Mpad + t0) * 64;
        int tx = tid & 15, ty = tid >> 4;
#pragma unroll
        for (int i = 0; i < 8; i++) {
            int r = ty * 8 + i;
            int t = t0 + r;
            if (t < M) {
                float pos = inc[t] * inv_len;
#pragma unroll
                for (int j = 0; j < 4; j++) {
                    int c = tx * 4 + j;
                    int jj = c & 31;
                    float ang = pos * theta[jj];
                    float sv, cv;
                    __sincosf(ang, &sv, &cv);
                    float x1 = Cs[r][jj], x2 = Cs[r][jj + 32];
                    float v = (c < 32) ? (x1 * cv - x2 * sv) : (x1 * sv + x2 * cv);
                    outp[(size_t)r * 64 + c] = __float2bfloat16(v);
                }
            } else {
#pragma unroll
                for (int j = 0; j < 4; j++)
                    outp[(size_t)r * 64 + tx * 4 + j] = __float2bfloat16(0.f);
            }
        }
    } else {
        bf16* outp = g_Vb + (size_t)(b * NH + h) * 64 * Mpad;
        int tt = tid & 127, db = (tid >> 7) * 32;
#pragma unroll
        for (int p = 0; p < 32; p++) {
            int d = db + p;
            outp[(size_t)d * Mpad + t0 + tt] = __float2bfloat16(Cs[tt][d]);
        }
    }
}

// ---------------------------------------------------------------------------
// FA2 attention, cp.async 2-stage K/V pipeline + mask preloaded.
// dyn smem: Qs 128x72 @0 (18432), Ks[2] 64x72 (18432), Vs[2] 64x72 (18432),
//           Ms 512 f32 (2048)  = 57344 B
// ---------------------------------------------------------------------------
__global__ void __launch_bounds__(256) attn_mma(const int* __restrict__ tmask)
{
    extern __shared__ __align__(16) char smraw[];
    bf16 (*Qs)[72]     = (bf16(*)[72])smraw;
    bf16 (*Ks)[64][72] = (bf16(*)[64][72])(smraw + 128 * 72 * 2);
    bf16 (*Vs)[64][72] = (bf16(*)[64][72])(smraw + (128 + 128) * 72 * 2);
    float* Ms          = (float*)(smraw + (128 + 256) * 72 * 2);

    const int qt = blockIdx.x, h = blockIdx.y, b = blockIdx.z;
    const int tid = threadIdx.x;
    const int wid = tid >> 5, lane = tid & 31;
    const int g = lane >> 2, tig = lane & 3;
    const int r0 = wid * 16;

    const int a_row = (lane & 7) + ((lane >> 3) & 1) * 8;
    const int a_col = (lane >> 4) * 8;
    const int b_row = ((lane >> 4) & 1) * 8 + (lane & 7);
    const int b_col = ((lane >> 3) & 1) * 8;

    const bf16* Qg = g_Qb + ((size_t)(b * NH + h) * TQPAD + qt * 128) * 64;
    const bf16* Kg = g_Kb + (size_t)(b * NH + h) * TTXT * 64;
    const bf16* Vg = g_Vb + (size_t)(b * NH + h) * 64 * TTXT;

    const int ar = tid >> 3, ac8 = (tid & 7) * 8;

    // prologue: Q + K/V tile 0 (one cp.async group), mask via regular LDG
#pragma unroll
    for (int p = 0; p < 4; p++)
        cp_async16(&Qs[ar + p * 32][ac8], &Qg[(size_t)(ar + p * 32) * 64 + ac8]);
#pragma unroll
    for (int p = 0; p < 2; p++) {
        int r = ar + p * 32;
        cp_async16(&Ks[0][r][ac8], &Kg[(size_t)r * 64 + ac8]);
        cp_async16(&Vs[0][r][ac8], &Vg[(size_t)r * TTXT + ac8]);
    }
    cp_commit();
#pragma unroll
    for (int p = 0; p < 2; p++)
        Ms[tid + p * 256] = (float)tmask[b * TTXT + tid + p * 256];

    float oc[8][4] = {};
    float m0v = -1e30f, m1v = -1e30f, l0 = 0.f, l1 = 0.f;
    uint32_t qa[4][4];

    for (int kt = 0; kt < TTXT / 64; kt++) {
        int cur = kt & 1;
        if (kt + 1 < TTXT / 64) {
            int nxt = cur ^ 1;
            int kb = (kt + 1) * 64;
#pragma unroll
            for (int p = 0; p < 2; p++) {
                int r = ar + p * 32;
                cp_async16(&Ks[nxt][r][ac8], &Kg[(size_t)(kb + r) * 64 + ac8]);
                cp_async16(&Vs[nxt][r][ac8], &Vg[(size_t)r * TTXT + kb + ac8]);
            }
            cp_commit();
            cp_wait<1>();
        } else {
            cp_wait<0>();
        }
        __syncthreads();

        if (kt == 0) {
#pragma unroll
            for (int kc = 0; kc < 4; kc++)
                ldsm_x4(qa[kc], &Qs[r0 + a_row][kc * 16 + a_col]);
        }

        // S = Q K^T
        float sc[8][4] = {};
#pragma unroll
        for (int kc = 0; kc < 4; kc++) {
#pragma unroll
            for (int np = 0; np < 4; np++) {
                uint32_t bb[4];
                ldsm_x4(bb, &Ks[cur][np * 16 + b_row][kc * 16 + b_col]);
                mma_bf16(sc[2 * np], qa[kc], bb);
                mma_bf16(sc[2 * np + 1], qa[kc], bb + 2);
            }
        }

        const float* Mt = Ms + kt * 64;
        float mx0 = -1e30f, mx1 = -1e30f;
#pragma unroll
        for (int ns = 0; ns < 8; ns++) {
            float mk0 = Mt[ns * 8 + 2 * tig], mk1 = Mt[ns * 8 + 2 * tig + 1];
            sc[ns][0] = (mk0 != 0.f) ? sc[ns][0] * SCALE_ATT : -1e30f;
            sc[ns][1] = (mk1 != 0.f) ? sc[ns][1] * SCALE_ATT : -1e30f;
            sc[ns][2] = (mk0 != 0.f) ? sc[ns][2] * SCALE_ATT : -1e30f;
            sc[ns][3] = (mk1 != 0.f) ? sc[ns][3] * SCALE_ATT : -1e30f;
            mx0 = fmaxf(mx0, fmaxf(sc[ns][0], sc[ns][1]));
            mx1 = fmaxf(mx1, fmaxf(sc[ns][2], sc[ns][3]));
        }
        mx0 = fmaxf(mx0, __shfl_xor_sync(~0u, mx0, 1));
        mx0 = fmaxf(mx0, __shfl_xor_sync(~0u, mx0, 2));
        mx1 = fmaxf(mx1, __shfl_xor_sync(~0u, mx1, 1));
        mx1 = fmaxf(mx1, __shfl_xor_sync(~0u, mx1, 2));

        float mn0 = fmaxf(m0v, mx0), mn1 = fmaxf(m1v, mx1);
        float corr0 = __expf(m0v - mn0), corr1 = __expf(m1v - mn1);
        m0v = mn0; m1v = mn1;

        float rs0 = 0.f, rs1 = 0.f;
#pragma unroll
        for (int ns = 0; ns < 8; ns++) {
            float e0 = (sc[ns][0] > -1e29f) ? __expf(sc[ns][0] - mn0) : 0.f;
            float e1 = (sc[ns][1] > -1e29f) ? __expf(sc[ns][1] - mn0) : 0.f;
            float e2 = (sc[ns][2] > -1e29f) ? __expf(sc[ns][2] - mn1) : 0.f;
            float e3 = (sc[ns][3] > -1e29f) ? __expf(sc[ns][3] - mn1) : 0.f;
            rs0 += e0 + e1; rs1 += e2 + e3;
            sc[ns][0] = e0; sc[ns][1] = e1; sc[ns][2] = e2; sc[ns][3] = e3;
        }
        rs0 += __shfl_xor_sync(~0u, rs0, 1);
        rs0 += __shfl_xor_sync(~0u, rs0, 2);
        rs1 += __shfl_xor_sync(~0u, rs1, 1);
        rs1 += __shfl_xor_sync(~0u, rs1, 2);
        l0 = l0 * corr0 + rs0;
        l1 = l1 * corr1 + rs1;

        uint32_t pa[4][4];
#pragma unroll
        for (int kc = 0; kc < 4; kc++) {
            pa[kc][0] = packbf2(sc[2 * kc][0], sc[2 * kc][1]);
            pa[kc][1] = packbf2(sc[2 * kc][2], sc[2 * kc][3]);
            pa[kc][2] = packbf2(sc[2 * kc + 1][0], sc[2 * kc + 1][1]);
            pa[kc][3] = packbf2(sc[2 * kc + 1][2], sc[2 * kc + 1][3]);
        }

#pragma unroll
        for (int ns = 0; ns < 8; ns++) {
            oc[ns][0] *= corr0; oc[ns][1] *= corr0;
            oc[ns][2] *= corr1; oc[ns][3] *= corr1;
        }
#pragma unroll
        for (int kc = 0; kc < 4; kc++) {
#pragma unroll
            for (int np = 0; np < 4; np++) {
                uint32_t vb[4];
                ldsm_x4(vb, &Vs[cur][np * 16 + b_row][kc * 16 + b_col]);
                mma_bf16(oc[2 * np], pa[kc], vb);
                mma_bf16(oc[2 * np + 1], pa[kc], vb + 2);
            }
        }
        __syncthreads();
    }

    float inv0 = 1.f / l0, inv1 = 1.f / l1;
    int tg = qt * 128 + r0 + g;
    bf16* Ob = g_Ob + (size_t)b * TQPAD * TDm + h * 64;
#pragma unroll
    for (int ns = 0; ns < 8; ns++) {
        int c = ns * 8 + 2 * tig;
        *(uint32_t*)&Ob[(size_t)tg * TDm + c] =
            packbf2(oc[ns][0] * inv0, oc[ns][1] * inv0);
        *(uint32_t*)&Ob[(size_t)(tg + 8) * TDm + c] =
            packbf2(oc[ns][2] * inv1, oc[ns][3] * inv1);
    }
}

// ---------------------------------------------------------------------------
// Output projection, cp.async 2-stage; + residual + bias + mask.
// ---------------------------------------------------------------------------
__global__ void __launch_bounds__(256) oproj_mma(
    const float* __restrict__ x, const float* __restrict__ bo,
    const float* __restrict__ lmask, float* __restrict__ out)
{
    extern __shared__ __align__(16) char smraw[];
    bf16 (*As)[128][72] = (bf16(*)[128][72])smraw;
    bf16 (*Bs)[64][72]  = (bf16(*)[64][72])(smraw + 2 * 128 * 72 * 2);
    float (*Cs)[65]     = (float(*)[65])smraw;

    const int b = blockIdx.z;
    const int t0 = blockIdx.x * 128;
    const int c0 = blockIdx.y * 64;
    const int tid = threadIdx.x;
    const int wid = tid >> 5, lane = tid & 31;
    const int g = lane >> 2, tig = lane & 3;
    const int m0 = (wid >> 1) * 32, n0 = (wid & 1) * 32;

    const int a_row = (lane & 7) + ((lane >> 3) & 1) * 8;
    const int a_col = (lane >> 4) * 8;
    const int b_row = ((lane >> 4) & 1) * 8 + (lane & 7);
    const int b_col = ((lane >> 3) & 1) * 8;

    const bf16* Ab = g_Ob + ((size_t)b * TQPAD + t0) * TDm;
    const bf16* Wb = g_Wob + (size_t)c0 * TDm;

    const int ar = tid >> 3, ac8 = (tid & 7) * 8;
    const int KT = TDm >> 6;   // 4

#pragma unroll
    for (int p = 0; p < 4; p++)
        cp_async16(&As[0][ar + p * 32][ac8], &Ab[(size_t)(ar + p * 32) * TDm + ac8]);
#pragma unroll
    for (int p = 0; p < 2; p++)
        cp_async16(&Bs[0][ar + p * 32][ac8], &Wb[(size_t)(ar + p * 32) * TDm + ac8]);
    cp_commit();

    float acc[2][4][4] = {};

    for (int kt = 0; kt < KT; kt++) {
        int cur = kt & 1;
        if (kt + 1 < KT) {
            int nxt = cur ^ 1;
            int k0 = (kt + 1) << 6;
#pragma unroll
            for (int p = 0; p < 4; p++)
                cp_async16(&As[nxt][ar + p * 32][ac8],
                           &Ab[(size_t)(ar + p * 32) * TDm + k0 + ac8]);
#pragma unroll
            for (int p = 0; p < 2; p++)
                cp_async16(&Bs[nxt][ar + p * 32][ac8],
                           &Wb[(size_t)(ar + p * 32) * TDm + k0 + ac8]);
            cp_commit();
            cp_wait<1>();
        } else {
            cp_wait<0>();
        }
        __syncthreads();

#pragma unroll
        for (int kc = 0; kc < 4; kc++) {
            uint32_t am[2][4];
            ldsm_x4(am[0], &As[cur][m0 + a_row][kc * 16 + a_col]);
            ldsm_x4(am[1], &As[cur][m0 + 16 + a_row][kc * 16 + a_col]);
#pragma unroll
            for (int np = 0; np < 2; np++) {
                uint32_t bb[4];
                ldsm_x4(bb, &Bs[cur][n0 + np * 16 + b_row][kc * 16 + b_col]);
                mma_bf16(acc[0][2 * np], am[0], bb);
                mma_bf16(acc[0][2 * np + 1], am[0], bb + 2);
                mma_bf16(acc[1][2 * np], am[1], bb);
                mma_bf16(acc[1][2 * np + 1], am[1], bb + 2);
            }
        }
        __syncthreads();
    }

#pragma unroll
    for (int ms = 0; ms < 2; ms++)
#pragma unroll
        for (int ns = 0; ns < 4; ns++) {
            int r = m0 + ms * 16 + g;
            int c = n0 + ns * 8 + 2 * tig;
            Cs[r][c]         = acc[ms][ns][0];
            Cs[r][c + 1]     = acc[ms][ns][1];
            Cs[r + 8][c]     = acc[ms][ns][2];
            Cs[r + 8][c + 1] = acc[ms][ns][3];
        }
    __syncthreads();

    int tt = tid & 127;
    int t = t0 + tt;
    if (t < TLAT) {
        float lm = lmask[(size_t)b * TLAT + t];
        int cb = (tid >> 7) * 32;
#pragma unroll
        for (int p = 0; p < 32; p++) {
            int cc = cb + p;
            int c = c0 + cc;
            size_t idx = ((size_t)b * CHN + c) * TLAT + t;
            out[idx] = (x[idx] + bo[c] + Cs[tt][cc]) * lm;
        }
    }
}

// ---------------------------------------------------------------------------
extern "C" void kernel_launch(void* const* d_in, const int* in_sizes, int n_in,
                              void* d_out, int out_size)
{
    const float* x     = (const float*)d_in[0];
    const float* temb  = (const float*)d_in[1];
    const float* lmask = (const float*)d_in[2];
    const int*   tmask = (const int*)d_in[3];
    const float* Wq    = (const float*)d_in[4];
    const float* bq    = (const float*)d_in[5];
    const float* Wk    = (const float*)d_in[6];
    const float* bk    = (const float*)d_in[7];
    const float* Wv    = (const float*)d_in[8];
    const float* bv    = (const float*)d_in[9];
    const float* Wo    = (const float*)d_in[10];
    const float* bo    = (const float*)d_in[11];
    const float* theta = (const float*)d_in[12];
    const float* inc   = (const float*)d_in[13];
    float* out = (float*)d_out;

    const int smem_proj = 2 * 128 * 72 * 2 + 2 * 64 * 72 * 2;   // 55296
    const int smem_attn = (128 + 256) * 72 * 2 + 512 * 4;       // 57344
    cudaFuncSetAttribute(proj_mma, cudaFuncAttributeMaxDynamicSharedMemorySize,
                         smem_proj);
    cudaFuncSetAttribute(attn_mma, cudaFuncAttributeMaxDynamicSharedMemorySize,
                         smem_attn);
    cudaFuncSetAttribute(oproj_mma, cudaFuncAttributeMaxDynamicSharedMemorySize,
                         smem_proj);

    transpose_bf<<<dim3(TQPAD / 32, CHN / 32, Bsz), dim3(32, 8)>>>(
        x, CHN, TLAT, TQPAD, 0);
    transpose_bf<<<dim3(TTXT / 32, TDm / 32, Bsz), dim3(32, 8)>>>(
        temb, TDm, TTXT, TTXT, 1);
    conv_weights<<<(TDm * CHN + 255) / 256, 256>>>(Wq, Wk, Wv, Wo);

    proj_mma<<<dim3(TQPAD / 128, NH, Bsz), 256, smem_proj>>>(
        bq, theta, inc, TQPAD, TLAT, CHN, 1.f / (float)TLAT, 0);
    proj_mma<<<dim3(TTXT / 128, NH, Bsz), 256, smem_proj>>>(
        bk, theta, inc, TTXT, TTXT, TDm, 1.f / (float)TTXT, 1);
    proj_mma<<<dim3(TTXT / 128, NH, Bsz), 256, smem_proj>>>(
        bv, theta, inc, TTXT, TTXT, TDm, 1.f / (float)TTXT, 2);

    attn_mma<<<dim3(TQPAD / 128, NH, Bsz), 256, smem_attn>>>(tmask);

    oproj_mma<<<dim3(TQPAD / 128, CHN / 64, Bsz), 256, smem_proj>>>(
        x, bo, lmask, out);
}